// round 10
// baseline (speedup 1.0000x reference)
#include <cuda_runtime.h>
#include <cstdint>

#define DEV __device__ __forceinline__
#define HDC __host__ __device__ constexpr
#define FULLMASK 0xffffffffu

// Rotation matrices for the 3 layers x 9 qubits, 8 floats each:
// [m00r, m00i, m01r, m01i, m10r, m10i, m11r, m11i]
__device__ float d_rotm[3 * 9 * 8];

// ---------------------------------------------------------------------------
// Prep kernel: build the 27 complex 2x2 rotation matrices from weights[3,9,3]
// ---------------------------------------------------------------------------
__global__ void prep_kernel(const float* __restrict__ w) {
    int t = threadIdx.x;
    if (t >= 27) return;
    float phi = w[t * 3 + 0], th = w[t * 3 + 1], om = w[t * 3 + 2];
    float s, c;   sincosf(0.5f * th, &s, &c);
    float sa, ca; sincosf(0.5f * (phi + om), &sa, &ca);
    float sb, cb; sincosf(0.5f * (phi - om), &sb, &cb);
    float* m = d_rotm + t * 8;
    m[0] =  c * ca;  m[1] = -c * sa;   // m00
    m[2] = -s * cb;  m[3] = -s * sb;   // m01
    m[4] =  s * cb;  m[5] = -s * sb;   // m10
    m[6] =  c * ca;  m[7] =  c * sa;   // m11
}

// ---------------------------------------------------------------------------
// GF(2) machinery. All helpers __host__ __device__ constexpr (no
// --expt-relaxed-constexpr needed), and all with SMALL step counts so nvcc's
// constexpr complexity limit is respected (9-bit inverse via Gauss-Jordan,
// not 512-entry brute force).
//
// CNOT(c_bit, t_bit) state action: v'[j] = v[f(j)], f(j)=j^(bit_c(j)<<t).
// Sequential gates g_first .. g_last compose with the LAST gate innermost:
// v_out[j] = v_in[ f_first(f_second(...f_last(j))) ].
//
// Lane virtualization: physical storage s relates to logical v by
// v[j] = s[Q(j)] with Q block-diagonal (lane bits only; locals identity).
// Skipping a pure-lane CNOT group physically updates Q <- Q o F_group.
// A rotation on logical bit b then uses physical pair distance d = Q(e_b)
// and role bit = parity(k & row_b(Q^-1)).
// ---------------------------------------------------------------------------
HDC int cx(int k, int c, int t) { return k ^ (((k >> c) & 1) << t); }

// Lane map after ring1's pure-lane group (index bits (8,7),(7,6),(6,5),(5,4)
// = lane bits (4,3),(3,2),(2,1),(1,0); first applied -> outermost).
HDC int Q1Lf(int k) {
    k = cx(k, 1, 0); k = cx(k, 2, 1); k = cx(k, 3, 2); k = cx(k, 4, 3);
    return k;
}
// Lane map after ring2's pure-lane group (lane gates (4,2),(3,1),(2,0))
// composed onto Q1L:  Q2L = Q1L o G2.
HDC int Q2Lf(int k) {
    k = cx(k, 2, 0); k = cx(k, 3, 1); k = cx(k, 4, 2);
    return Q1Lf(k);
}
HDC int lmap(int which, int k) { return which == 1 ? Q1Lf(k) : Q2Lf(k); }

HDC int parity9(int x) { int c = 0; for (int i = 0; i < 9; i++) c ^= (x >> i) & 1; return c; }

// Inverse images / rows of inverse for the 5-bit lane maps (32-entry scan: cheap).
HDC int linv5img(int which, int p) {
    for (int k = 0; k < 32; k++) if (lmap(which, k) == (1 << p)) return k;
    return -1;
}
HDC int lrow5(int which, int b) {
    int m = 0;
    for (int p = 0; p < 5; p++) if ((linv5img(which, p) >> b) & 1) m |= 1 << p;
    return m;
}
// Consistency: parity(Q(e_be) & row_b(Q^-1)) == delta(b,be)
HDC bool check5(int which) {
    for (int b = 0; b < 5; b++)
        for (int be = 0; be < 5; be++)
            if (parity9(lmap(which, 1 << be) & lrow5(which, b)) != ((b == be) ? 1 : 0))
                return false;
    return true;
}
static_assert(check5(1), "Q1L inverse rows inconsistent");
static_assert(check5(2), "Q2L inverse rows inconsistent");

// Full 9-bit map for measurement: Qfull = Qb o F3, Qb = Q2L on lanes.
// Ring r gate i: control bit 8-i, target bit 8-((i+r)%9); i=0 outermost.
HDC int ringF3(int k) {
    for (int i = 8; i >= 0; i--) k = cx(k, 8 - i, 8 - ((i + 3) % 9));
    return k;
}
HDC int Qfullf(int j) {
    int t = ringF3(j);
    return (Q2Lf(t >> 4) << 4) | (t & 15);
}

// Row b of Qfull^-1 over GF(2), via Gauss-Jordan (9x9, rows as bitmasks).
// M's columns are Qfullf(e_j). After reduction, aug[b] = row b of M^-1:
// bit_b(Qfull^-1(k)) = parity(k & invrow9(b)).
HDC int invrow9(int b) {
    int rows[9] = {}, aug[9] = {};
    for (int i = 0; i < 9; i++) {
        int r = 0;
        for (int j = 0; j < 9; j++) r |= ((Qfullf(1 << j) >> i) & 1) << j;
        rows[i] = r;
        aug[i]  = 1 << i;
    }
    for (int c2 = 0; c2 < 9; c2++) {
        int piv = -1;
        for (int r2 = c2; r2 < 9; r2++)
            if ((rows[r2] >> c2) & 1) { piv = r2; break; }
        if (piv < 0) return -1;  // singular (impossible for CNOT circuits)
        int tr = rows[c2]; rows[c2] = rows[piv]; rows[piv] = tr;
        int ta = aug[c2];  aug[c2]  = aug[piv];  aug[piv]  = ta;
        for (int r2 = 0; r2 < 9; r2++)
            if (r2 != c2 && ((rows[r2] >> c2) & 1)) {
                rows[r2] ^= rows[c2];
                aug[r2]  ^= aug[c2];
            }
    }
    return aug[b];
}
HDC int measrow(int b) { return invrow9(b); }

// Verify M^-1 * M = I: parity(col_j(M) & row_b(M^-1)) == delta(b,j).
HDC bool check9() {
    for (int b = 0; b < 9; b++) {
        int rb = invrow9(b);
        if (rb < 0) return false;
        for (int j = 0; j < 9; j++)
            if (parity9(Qfullf(1 << j) & rb) != ((j == b) ? 1 : 0))
                return false;
    }
    return true;
}
static_assert(check9(), "full measurement map inconsistent");

// ---------------------------------------------------------------------------
// Warp-level statevector primitives. Amplitude index (9b) = lane(5b)|local(4b).
// ---------------------------------------------------------------------------

// Rotation on a LOCAL bit B (0..3): in-register 2x2 matvecs.
template <int B>
DEV void rot_local(float* ar, float* ai, const float* __restrict__ m) {
    float m00r = m[0], m00i = m[1], m01r = m[2], m01i = m[3];
    float m10r = m[4], m10i = m[5], m11r = m[6], m11i = m[7];
#pragma unroll
    for (int l = 0; l < 16; l++) {
        if (!(l & (1 << B))) {
            int l2 = l | (1 << B);
            float a0r = ar[l], a0i = ai[l], a1r = ar[l2], a1i = ai[l2];
            ar[l]  = m00r * a0r - m00i * a0i + m01r * a1r - m01i * a1i;
            ai[l]  = m00r * a0i + m00i * a0r + m01r * a1i + m01i * a1r;
            ar[l2] = m10r * a0r - m10i * a0i + m11r * a1r - m11i * a1i;
            ai[l2] = m10r * a0i + m10i * a0r + m11r * a1i + m11i * a1r;
        }
    }
}

// Generalized lane rotation under relabeling:
//   DPAT: physical shfl_xor pattern = Q(e_b) (pure lane bits)
//   RMASK: role = parity(lane & RMASK) (row of Q^-1)
//   SWAPMASK: bit l set -> local l has a merged preceding CNOT whose control
//             (a physical local bit) is set: own/partner coefficients swap.
template <int DPAT, int RMASK, int SWAPMASK>
DEV void rot_lane_g(float* ar, float* ai, const float* __restrict__ m, int lane) {
    bool r = __popc(lane & RMASK) & 1;
    float ownR = r ? m[6] : m[0];
    float ownI = r ? m[7] : m[1];
    float parR = r ? m[4] : m[2];
    float parI = r ? m[5] : m[3];
#pragma unroll
    for (int l = 0; l < 16; l++) {
        float pr = __shfl_xor_sync(FULLMASK, ar[l], DPAT);
        float pi = __shfl_xor_sync(FULLMASK, ai[l], DPAT);
        const bool sw = (SWAPMASK >> l) & 1;      // compile-time after unroll
        float aR = sw ? parR : ownR, aI = sw ? parI : ownI;
        float bR = sw ? ownR : parR, bI = sw ? ownI : parI;
        float a = ar[l], bq = ai[l];
        ar[l] = aR * a - aI * bq + bR * pr - bI * pi;
        ai[l] = aR * bq + aI * a + bR * pi + bI * pr;
    }
}

// CNOT with (relabeled) lane-parity control CMASK, physical local target TB.
template <int CMASK, int TB>
DEV void cnot_lpar_local(float* ar, float* ai, int lane) {
    bool c = __popc(lane & CMASK) & 1;
#pragma unroll
    for (int l = 0; l < 16; l++) {
        if (!((l >> TB) & 1)) {
            int l2 = l | (1 << TB);
            float t0r = ar[l], t1r = ar[l2], t0i = ai[l], t1i = ai[l2];
            ar[l]  = c ? t1r : t0r;  ar[l2] = c ? t0r : t1r;
            ai[l]  = c ? t1i : t0i;  ai[l2] = c ? t0i : t1i;
        }
    }
}

// Local-local CNOT: compile-time register pair swaps (free).
template <int CB, int TB>
DEV void cnot_local(float* ar, float* ai) {
#pragma unroll
    for (int l = 0; l < 16; l++) {
        if (((l >> CB) & 1) && !((l >> TB) & 1)) {
            int l2 = l | (1 << TB);
            float t;
            t = ar[l]; ar[l] = ar[l2]; ar[l2] = t;
            t = ai[l]; ai[l] = ai[l2]; ai[l2] = t;
        }
    }
}

// kron doubling step: T[2i+j] = T[i] * q[j], in place (descending i).
template <int CNT>
DEV void kron_step(float* Tr, float* Ti,
                   float q0r, float q0i, float q1r, float q1i) {
#pragma unroll
    for (int i = CNT - 1; i >= 0; i--) {
        float tr = Tr[i], ti = Ti[i];
        Tr[2 * i + 1] = tr * q1r - ti * q1i;
        Ti[2 * i + 1] = tr * q1i + ti * q1r;
        Tr[2 * i]     = tr * q0r - ti * q0i;
        Ti[2 * i]     = tr * q0i + ti * q0r;
    }
}

// q'_w = R(layer0, qubit w) @ [cos(x/2), -i sin(x/2)]
DEV void load_q(const float* __restrict__ xb, const float* __restrict__ rot0,
                int w, float& q0r, float& q0i, float& q1r, float& q1i) {
    float sh, ch;
    __sincosf(0.5f * xb[w], &sh, &ch);
    const float* m = rot0 + w * 8;
    q0r = m[0] * ch + m[3] * sh;
    q0i = m[1] * ch - m[2] * sh;
    q1r = m[4] * ch + m[7] * sh;
    q1i = m[5] * ch - m[6] * sh;
}

// Measurement for output qubit Q; mask folds Q2L-relabel + final CNOT ring.
template <int Q>
DEV void meas_q(const float* p, int lane, float& outv) {
    constexpr int M  = measrow(8 - Q);
    constexpr int LO = M & 15;
    constexpr int HI = (M >> 4) & 31;
    float s = 0.f;
#pragma unroll
    for (int l = 0; l < 16; l++) {
        if (__popc(l & LO) & 1) s -= p[l]; else s += p[l];
    }
    if (__popc(lane & HI) & 1) s = -s;
#pragma unroll
    for (int off = 16; off; off >>= 1) s += __shfl_xor_sync(FULLMASK, s, off);
    outv = s;
}

// ---------------------------------------------------------------------------
// Main kernel: one warp per sample.
// ---------------------------------------------------------------------------
__global__ void __launch_bounds__(256)
sim_kernel(const float* __restrict__ x, float* __restrict__ out, int nsamples) {
    __shared__ float srot[3 * 9 * 8];
    if (threadIdx.x < 3 * 9 * 8) srot[threadIdx.x] = d_rotm[threadIdx.x];
    __syncthreads();

    const int lane = threadIdx.x & 31;
    const int warp = threadIdx.x >> 5;
    const int b = blockIdx.x * 8 + warp;
    if (b >= nsamples) return;
    const float* xb = x + b * 9;

    float ar[16], ai[16];

    // ---- Product state with layer-0 rotations folded in (physical coords) ----
    float Fr = 1.f, Fi = 0.f;
#pragma unroll
    for (int w = 0; w < 5; w++) {
        float q0r, q0i, q1r, q1i;
        load_q(xb, srot, w, q0r, q0i, q1r, q1i);
        bool bit = (lane >> (4 - w)) & 1;
        float qr = bit ? q1r : q0r, qi = bit ? q1i : q0i;
        float nr = Fr * qr - Fi * qi;
        Fi = Fr * qi + Fi * qr;
        Fr = nr;
    }
    ar[0] = 1.f; ai[0] = 0.f;
    {
        float q0r, q0i, q1r, q1i;
        load_q(xb, srot, 5, q0r, q0i, q1r, q1i); kron_step<1>(ar, ai, q0r, q0i, q1r, q1i);
        load_q(xb, srot, 6, q0r, q0i, q1r, q1i); kron_step<2>(ar, ai, q0r, q0i, q1r, q1i);
        load_q(xb, srot, 7, q0r, q0i, q1r, q1i); kron_step<4>(ar, ai, q0r, q0i, q1r, q1i);
        load_q(xb, srot, 8, q0r, q0i, q1r, q1i); kron_step<8>(ar, ai, q0r, q0i, q1r, q1i);
    }
#pragma unroll
    for (int l = 0; l < 16; l++) {
        float nr = Fr * ar[l] - Fi * ai[l];
        ai[l] = Fr * ai[l] + Fi * ar[l];
        ar[l] = nr;
    }

    // ---- Ring r=1 ----
    // (8,7),(7,6),(6,5),(5,4): pure-lane group -> VIRTUAL (relabel Q1L).
    // (4,3): control logical bit4 (lane beta0 under Q1L), target local bit3.
    cnot_lpar_local<lrow5(1, 0), 3>(ar, ai, lane);
    cnot_local<3, 2>(ar, ai);
    cnot_local<2, 1>(ar, ai);
    cnot_local<1, 0>(ar, ai);
    // (0,8): merged into layer-1 qubit0 rotation below (SWAPMASK local bit0).

    // ---- Rotation layer 1 (under relabel Q1L) ----
    {
        const float* rm = srot + 1 * 72;
        rot_lane_g<lmap(1, 16), lrow5(1, 4), 0xAAAA>(ar, ai, rm + 0 * 8, lane); // qubit0 (+CNOT(0,8))
        rot_lane_g<lmap(1,  8), lrow5(1, 3), 0>(ar, ai, rm + 1 * 8, lane);      // qubit1
        rot_lane_g<lmap(1,  4), lrow5(1, 2), 0>(ar, ai, rm + 2 * 8, lane);      // qubit2
        rot_lane_g<lmap(1,  2), lrow5(1, 1), 0>(ar, ai, rm + 3 * 8, lane);      // qubit3
        rot_lane_g<lmap(1,  1), lrow5(1, 0), 0>(ar, ai, rm + 4 * 8, lane);      // qubit4
        rot_local<3>(ar, ai, rm + 5 * 8);                                       // qubit5
        rot_local<2>(ar, ai, rm + 6 * 8);                                       // qubit6
        rot_local<1>(ar, ai, rm + 7 * 8);                                       // qubit7
        rot_local<0>(ar, ai, rm + 8 * 8);                                       // qubit8
    }

    // ---- Ring r=2 ----
    // (8,6),(7,5),(6,4): pure-lane group -> VIRTUAL (relabel now Q2L).
    // (5,3): control logical bit5 (lane beta1 under Q2L), target local bit3.
    cnot_lpar_local<lrow5(2, 1), 3>(ar, ai, lane);
    // (4,2): control logical bit4 (lane beta0), target local bit2.
    cnot_lpar_local<lrow5(2, 0), 2>(ar, ai, lane);
    cnot_local<3, 1>(ar, ai);
    cnot_local<2, 0>(ar, ai);
    // (1,8) merged into layer-2 qubit0 rot (local bit1); (0,7) into qubit1 rot (bit0).

    // ---- Rotation layer 2 (under relabel Q2L) ----
    {
        const float* rm = srot + 2 * 72;
        rot_lane_g<lmap(2, 16), lrow5(2, 4), 0xCCCC>(ar, ai, rm + 0 * 8, lane); // qubit0 (+CNOT(1,8))
        rot_lane_g<lmap(2,  8), lrow5(2, 3), 0xAAAA>(ar, ai, rm + 1 * 8, lane); // qubit1 (+CNOT(0,7))
        rot_lane_g<lmap(2,  4), lrow5(2, 2), 0>(ar, ai, rm + 2 * 8, lane);      // qubit2
        rot_lane_g<lmap(2,  2), lrow5(2, 1), 0>(ar, ai, rm + 3 * 8, lane);      // qubit3
        rot_lane_g<lmap(2,  1), lrow5(2, 0), 0>(ar, ai, rm + 4 * 8, lane);      // qubit4
        rot_local<3>(ar, ai, rm + 5 * 8);
        rot_local<2>(ar, ai, rm + 6 * 8);
        rot_local<1>(ar, ai, rm + 7 * 8);
        rot_local<0>(ar, ai, rm + 8 * 8);
    }

    // ---- Measurement (relabel + final CNOT ring folded into parity masks) ----
    float p[16];
#pragma unroll
    for (int l = 0; l < 16; l++) p[l] = ar[l] * ar[l] + ai[l] * ai[l];

    float r0, r1, r2, r3, r4, r5, r6, r7, r8;
    meas_q<0>(p, lane, r0);
    meas_q<1>(p, lane, r1);
    meas_q<2>(p, lane, r2);
    meas_q<3>(p, lane, r3);
    meas_q<4>(p, lane, r4);
    meas_q<5>(p, lane, r5);
    meas_q<6>(p, lane, r6);
    meas_q<7>(p, lane, r7);
    meas_q<8>(p, lane, r8);

    // All lanes hold all reduced sums; lanes 0..8 write one output each via a
    // static select chain (no local-memory spill from dynamic indexing).
    if (lane < 9) {
        float v = (lane == 0) ? r0 : (lane == 1) ? r1 : (lane == 2) ? r2 :
                  (lane == 3) ? r3 : (lane == 4) ? r4 : (lane == 5) ? r5 :
                  (lane == 6) ? r6 : (lane == 7) ? r7 : r8;
        out[b * 9 + lane] = v;
    }
}

extern "C" void kernel_launch(void* const* d_in, const int* in_sizes, int n_in,
                              void* d_out, int out_size) {
    const float* x = (const float*)d_in[0];       // [nsamples, 9] fp32
    const float* w = (const float*)d_in[1];       // [3, 9, 3] fp32
    float* out = (float*)d_out;                   // [nsamples, 9] fp32
    int nsamples = in_sizes[0] / 9;

    prep_kernel<<<1, 32>>>(w);
    int nblocks = (nsamples + 7) / 8;
    sim_kernel<<<nblocks, 256>>>(x, out, nsamples);
}

// round 13
// speedup vs baseline: 1.0904x; 1.0904x over previous
#include <cuda_runtime.h>
#include <cstdint>

#define DEV __device__ __forceinline__
#define HDC __host__ __device__ constexpr
#define FULLMASK 0xffffffffu

typedef unsigned long long ull;

// Rotation matrices for the 3 layers x 9 qubits, 8 floats each:
// [m00r, m00i, m01r, m01i, m10r, m10i, m11r, m11i]
__device__ float d_rotm[3 * 9 * 8];

// ---------------------------------------------------------------------------
// Prep kernel: build the 27 complex 2x2 rotation matrices from weights[3,9,3]
// ---------------------------------------------------------------------------
__global__ void prep_kernel(const float* __restrict__ w) {
    int t = threadIdx.x;
    if (t >= 27) return;
    float phi = w[t * 3 + 0], th = w[t * 3 + 1], om = w[t * 3 + 2];
    float s, c;   sincosf(0.5f * th, &s, &c);
    float sa, ca; sincosf(0.5f * (phi + om), &sa, &ca);
    float sb, cb; sincosf(0.5f * (phi - om), &sb, &cb);
    float* m = d_rotm + t * 8;
    m[0] =  c * ca;  m[1] = -c * sa;   // m00
    m[2] = -s * cb;  m[3] = -s * sb;   // m01
    m[4] =  s * cb;  m[5] = -s * sb;   // m10
    m[6] =  c * ca;  m[7] =  c * sa;   // m11
}

// ---------------------------------------------------------------------------
// GF(2) machinery (all HDC; small step counts -> no constexpr-limit issues).
// See R2-R9 derivations. Amplitude index (9b) = lane(5b) | local(4b).
// ---------------------------------------------------------------------------
HDC int cx(int k, int c, int t) { return k ^ (((k >> c) & 1) << t); }

HDC int Q1Lf(int k) {
    k = cx(k, 1, 0); k = cx(k, 2, 1); k = cx(k, 3, 2); k = cx(k, 4, 3);
    return k;
}
HDC int Q2Lf(int k) {
    k = cx(k, 2, 0); k = cx(k, 3, 1); k = cx(k, 4, 2);
    return Q1Lf(k);
}
HDC int lmap(int which, int k) { return which == 1 ? Q1Lf(k) : Q2Lf(k); }

HDC int parity9(int x) { int c = 0; for (int i = 0; i < 9; i++) c ^= (x >> i) & 1; return c; }

HDC int linv5img(int which, int p) {
    for (int k = 0; k < 32; k++) if (lmap(which, k) == (1 << p)) return k;
    return -1;
}
HDC int lrow5(int which, int b) {
    int m = 0;
    for (int p = 0; p < 5; p++) if ((linv5img(which, p) >> b) & 1) m |= 1 << p;
    return m;
}
HDC bool check5(int which) {
    for (int b = 0; b < 5; b++)
        for (int be = 0; be < 5; be++)
            if (parity9(lmap(which, 1 << be) & lrow5(which, b)) != ((b == be) ? 1 : 0))
                return false;
    return true;
}
static_assert(check5(1), "Q1L inverse rows inconsistent");
static_assert(check5(2), "Q2L inverse rows inconsistent");

HDC int ringF3(int k) {
    for (int i = 8; i >= 0; i--) k = cx(k, 8 - i, 8 - ((i + 3) % 9));
    return k;
}
HDC int Qfullf(int j) {
    int t = ringF3(j);
    return (Q2Lf(t >> 4) << 4) | (t & 15);
}
// Row b of Qfull^-1 over GF(2) via Gauss-Jordan (9x9, rows as bitmasks).
HDC int invrow9(int b) {
    int rows[9] = {}, aug[9] = {};
    for (int i = 0; i < 9; i++) {
        int r = 0;
        for (int j = 0; j < 9; j++) r |= ((Qfullf(1 << j) >> i) & 1) << j;
        rows[i] = r;
        aug[i]  = 1 << i;
    }
    for (int c2 = 0; c2 < 9; c2++) {
        int piv = -1;
        for (int r2 = c2; r2 < 9; r2++)
            if ((rows[r2] >> c2) & 1) { piv = r2; break; }
        if (piv < 0) return -1;
        int tr = rows[c2]; rows[c2] = rows[piv]; rows[piv] = tr;
        int ta = aug[c2];  aug[c2]  = aug[piv];  aug[piv]  = ta;
        for (int r2 = 0; r2 < 9; r2++)
            if (r2 != c2 && ((rows[r2] >> c2) & 1)) {
                rows[r2] ^= rows[c2];
                aug[r2]  ^= aug[c2];
            }
    }
    return aug[b];
}
HDC int measrow(int b) { return invrow9(b); }
HDC bool check9() {
    for (int b = 0; b < 9; b++) {
        int rb = invrow9(b);
        if (rb < 0) return false;
        for (int j = 0; j < 9; j++)
            if (parity9(Qfullf(1 << j) & rb) != ((j == b) ? 1 : 0))
                return false;
    }
    return true;
}
static_assert(check9(), "full measurement map inconsistent");

// ---------------------------------------------------------------------------
// Packed f32x2 primitives (sm_103a FFMA2 path; only reachable via PTX).
// State: 16 complex amps/lane packed as 8 ull regs each for re/im:
//   reg p holds locals (2p, 2p+1) in (lo, hi) halves.
// ---------------------------------------------------------------------------
DEV ull pk2(float lo, float hi) {
    ull o;
    asm("mov.b64 %0, {%1, %2};" : "=l"(o) : "r"(__float_as_uint(lo)), "r"(__float_as_uint(hi)));
    return o;
}
DEV void upk2(ull v, float& lo, float& hi) {
    unsigned a, b2;
    asm("mov.b64 {%0, %1}, %2;" : "=r"(a), "=r"(b2) : "l"(v));
    lo = __uint_as_float(a); hi = __uint_as_float(b2);
}
DEV ull bc2(float x) { return pk2(x, x); }
DEV ull swap2(ull v) { float lo, hi; upk2(v, lo, hi); return pk2(hi, lo); }
DEV ull f2fma(ull a, ull b, ull c) {
    ull o;
    asm("fma.rn.f32x2 %0, %1, %2, %3;" : "=l"(o) : "l"(a), "l"(b), "l"(c));
    return o;
}
DEV ull f2mul(ull a, ull b) {
    ull o;
    asm("mul.rn.f32x2 %0, %1, %2;" : "=l"(o) : "l"(a), "l"(b));
    return o;
}
DEV ull f2add(ull a, ull b) {
    ull o;
    asm("add.rn.f32x2 %0, %1, %2;" : "=l"(o) : "l"(a), "l"(b));
    return o;
}
DEV ull shfl64(ull v, int pat) {
    float lo, hi; upk2(v, lo, hi);
    lo = __shfl_xor_sync(FULLMASK, lo, pat);
    hi = __shfl_xor_sync(FULLMASK, hi, pat);
    return pk2(lo, hi);
}

// Rotation on LOCAL bit B (1..3): partner is another packed reg (same halves).
template <int B>
DEV void rot_local_pk(ull* aR, ull* aI, const float* __restrict__ m) {
    ull m00r = bc2(m[0]), m00i = bc2(m[1]), nm00i = bc2(-m[1]);
    ull m01r = bc2(m[2]), m01i = bc2(m[3]), nm01i = bc2(-m[3]);
    ull m10r = bc2(m[4]), m10i = bc2(m[5]), nm10i = bc2(-m[5]);
    ull m11r = bc2(m[6]), m11i = bc2(m[7]), nm11i = bc2(-m[7]);
    constexpr int d = 1 << (B - 1);
#pragma unroll
    for (int p = 0; p < 8; p++) {
        if (!(p & d)) {
            int p2 = p | d;
            ull a0r = aR[p], a0i = aI[p], a1r = aR[p2], a1i = aI[p2];
            aR[p]  = f2fma(m00r, a0r, f2fma(nm00i, a0i, f2fma(m01r, a1r, f2mul(nm01i, a1i))));
            aI[p]  = f2fma(m00r, a0i, f2fma(m00i,  a0r, f2fma(m01r, a1i, f2mul(m01i,  a1r))));
            aR[p2] = f2fma(m10r, a0r, f2fma(nm10i, a0i, f2fma(m11r, a1r, f2mul(nm11i, a1i))));
            aI[p2] = f2fma(m10r, a0i, f2fma(m10i,  a0r, f2fma(m11r, a1i, f2mul(m11i,  a1r))));
        }
    }
}

// Rotation on LOCAL bit 0: v0/v1 are the two halves of each packed reg.
DEV void rot_local0_pk(ull* aR, ull* aI, const float* __restrict__ m) {
    ull c0r = pk2(m[0], m[4]);
    ull c0i = pk2(m[1], m[5]), nc0i = pk2(-m[1], -m[5]);
    ull c1r = pk2(m[2], m[6]);
    ull c1i = pk2(m[3], m[7]), nc1i = pk2(-m[3], -m[7]);
#pragma unroll
    for (int p = 0; p < 8; p++) {
        float a0r, a1r, a0i, a1i;
        upk2(aR[p], a0r, a1r); upk2(aI[p], a0i, a1i);
        ull A0R = bc2(a0r), A1R = bc2(a1r), A0I = bc2(a0i), A1I = bc2(a1i);
        aR[p] = f2fma(c0r, A0R, f2fma(nc0i, A0I, f2fma(c1r, A1R, f2mul(nc1i, A1I))));
        aI[p] = f2fma(c0r, A0I, f2fma(c0i,  A0R, f2fma(c1r, A1I, f2mul(c1i,  A1R))));
    }
}

// Lane rotation under relabeling (see R2 derivation). SWAPMASK bit l:
// merged preceding local-control CNOT -> own/partner coefficient swap.
template <int DPAT, int RMASK, int SWAPMASK>
DEV void rot_lane_pk(ull* aR, ull* aI, const float* __restrict__ m, int lane) {
    bool r = __popc(lane & RMASK) & 1;
    float ownR = r ? m[6] : m[0];
    float ownI = r ? m[7] : m[1];
    float parR = r ? m[4] : m[2];
    float parI = r ? m[5] : m[3];
    // pattern packs (unused ones dead-code eliminated):
    ull OR00 = pk2(ownR, ownR), OR01 = pk2(ownR, parR), OR11 = pk2(parR, parR);
    ull OI00 = pk2(ownI, ownI), OI01 = pk2(ownI, parI), OI11 = pk2(parI, parI);
    ull nOI00 = pk2(-ownI, -ownI), nOI01 = pk2(-ownI, -parI), nOI11 = pk2(-parI, -parI);
    ull PR00 = pk2(parR, parR), PR01 = pk2(parR, ownR), PR11 = pk2(ownR, ownR);
    ull PI00 = pk2(parI, parI), PI01 = pk2(parI, ownI), PI11 = pk2(ownI, ownI);
    ull nPI00 = pk2(-parI, -parI), nPI01 = pk2(-parI, -ownI), nPI11 = pk2(-ownI, -ownI);
#pragma unroll
    for (int p = 0; p < 8; p++) {
        const bool s0 = (SWAPMASK >> (2 * p)) & 1;
        const bool s1 = (SWAPMASK >> (2 * p + 1)) & 1;
        const int pat = (s0 ? 1 : 0) | (s1 ? 2 : 0);   // 0=(0,0), 2=(0,1), 3=(1,1)
        ull OCR  = (pat == 0) ? OR00  : (pat == 2) ? OR01  : OR11;
        ull OCI  = (pat == 0) ? OI00  : (pat == 2) ? OI01  : OI11;
        ull nOCI = (pat == 0) ? nOI00 : (pat == 2) ? nOI01 : nOI11;
        ull PCR  = (pat == 0) ? PR00  : (pat == 2) ? PR01  : PR11;
        ull PCI  = (pat == 0) ? PI00  : (pat == 2) ? PI01  : PI11;
        ull nPCI = (pat == 0) ? nPI00 : (pat == 2) ? nPI01 : nPI11;
        ull prr = shfl64(aR[p], DPAT);
        ull pii = shfl64(aI[p], DPAT);
        ull a = aR[p], bq = aI[p];
        aR[p] = f2fma(OCR, a,  f2fma(nOCI, bq, f2fma(PCR, prr, f2mul(nPCI, pii))));
        aI[p] = f2fma(OCR, bq, f2fma(OCI,  a,  f2fma(PCR, pii, f2mul(PCI,  prr))));
    }
}

// CNOT with lane-parity control CMASK, local target TB (2 or 3): packed-reg selects.
template <int CMASK, int TB>
DEV void cnot_lpar_pk(ull* aR, ull* aI, int lane) {
    bool c = __popc(lane & CMASK) & 1;
    constexpr int d = 1 << (TB - 1);
#pragma unroll
    for (int p = 0; p < 8; p++) {
        if (!(p & d)) {
            int p2 = p | d;
            ull t0 = aR[p], t1 = aR[p2];
            aR[p] = c ? t1 : t0;  aR[p2] = c ? t0 : t1;
            ull u0 = aI[p], u1 = aI[p2];
            aI[p] = c ? u1 : u0;  aI[p2] = c ? u0 : u1;
        }
    }
}

// Local-local CNOT. TB>=1: pure packed-reg renames (free). TB==0: half swaps.
template <int CB, int TB>
DEV void cnot_local_pk(ull* aR, ull* aI) {
    if constexpr (TB >= 1) {
        constexpr int cb = CB - 1, tb = TB - 1;
#pragma unroll
        for (int p = 0; p < 8; p++) {
            if (((p >> cb) & 1) && !((p >> tb) & 1)) {
                int p2 = p | (1 << tb);
                ull t;
                t = aR[p]; aR[p] = aR[p2]; aR[p2] = t;
                t = aI[p]; aI[p] = aI[p2]; aI[p2] = t;
            }
        }
    } else {
        constexpr int cb = CB - 1;
#pragma unroll
        for (int p = 0; p < 8; p++) {
            if ((p >> cb) & 1) { aR[p] = swap2(aR[p]); aI[p] = swap2(aI[p]); }
        }
    }
}

// kron doubling (scalar, small counts only).
template <int CNT>
DEV void kron_step(float* Tr, float* Ti,
                   float q0r, float q0i, float q1r, float q1i) {
#pragma unroll
    for (int i = CNT - 1; i >= 0; i--) {
        float tr = Tr[i], ti = Ti[i];
        Tr[2 * i + 1] = tr * q1r - ti * q1i;
        Ti[2 * i + 1] = tr * q1i + ti * q1r;
        Tr[2 * i]     = tr * q0r - ti * q0i;
        Ti[2 * i]     = tr * q0i + ti * q0r;
    }
}

// q'_w = R(layer0, qubit w) @ [cos(x/2), -i sin(x/2)]
DEV void load_q(const float* __restrict__ xb, const float* __restrict__ rot0,
                int w, float& q0r, float& q0i, float& q1r, float& q1i) {
    float sh, ch;
    __sincosf(0.5f * xb[w], &sh, &ch);
    const float* m = rot0 + w * 8;
    q0r = m[0] * ch + m[3] * sh;
    q0i = m[1] * ch - m[2] * sh;
    q1r = m[4] * ch + m[7] * sh;
    q1i = m[5] * ch - m[6] * sh;
}

// Measurement for output qubit Q (packed accumulate then fold).
// sign(l=2p+h) = parity(p & (LO>>1)) XOR (h & LO & 1); lane part via HI mask.
template <int Q>
DEV void meas_pk(const ull* p2, int lane, float& outv) {
    constexpr int M  = measrow(8 - Q);
    constexpr int LO = M & 15;
    constexpr int HI = (M >> 4) & 31;
    ull neg1 = bc2(-1.0f);
    ull acc = p2[0];                       // parity(0)=0 -> +
#pragma unroll
    for (int p = 1; p < 8; p++) {
        if (parity9(p & (LO >> 1)))
            acc = f2fma(neg1, p2[p], acc);
        else
            acc = f2add(acc, p2[p]);
    }
    float lo, hi; upk2(acc, lo, hi);
    float s = (LO & 1) ? (lo - hi) : (lo + hi);
    if (__popc(lane & HI) & 1) s = -s;
#pragma unroll
    for (int off = 16; off; off >>= 1) s += __shfl_xor_sync(FULLMASK, s, off);
    outv = s;
}

// ---------------------------------------------------------------------------
// Main kernel: one warp per sample.
// ---------------------------------------------------------------------------
__global__ void __launch_bounds__(256)
sim_kernel(const float* __restrict__ x, float* __restrict__ out, int nsamples) {
    __shared__ float srot[3 * 9 * 8];
    if (threadIdx.x < 3 * 9 * 8) srot[threadIdx.x] = d_rotm[threadIdx.x];
    __syncthreads();

    const int lane = threadIdx.x & 31;
    const int warp = threadIdx.x >> 5;
    const int b = blockIdx.x * 8 + warp;
    if (b >= nsamples) return;
    const float* xb = x + b * 9;

    // ---- Product state with layer-0 rotations folded in (physical coords) ----
    float Fr = 1.f, Fi = 0.f;
#pragma unroll
    for (int w = 0; w < 5; w++) {
        float q0r, q0i, q1r, q1i;
        load_q(xb, srot, w, q0r, q0i, q1r, q1i);
        bool bit = (lane >> (4 - w)) & 1;
        float qr = bit ? q1r : q0r, qi = bit ? q1i : q0i;
        float nr = Fr * qr - Fi * qi;
        Fi = Fr * qi + Fi * qr;
        Fr = nr;
    }
    float Tr[8], Ti[8];
    Tr[0] = 1.f; Ti[0] = 0.f;
    ull aR[8], aI[8];
    {
        float q0r, q0i, q1r, q1i;
        load_q(xb, srot, 5, q0r, q0i, q1r, q1i); kron_step<1>(Tr, Ti, q0r, q0i, q1r, q1i);
        load_q(xb, srot, 6, q0r, q0i, q1r, q1i); kron_step<2>(Tr, Ti, q0r, q0i, q1r, q1i);
        load_q(xb, srot, 7, q0r, q0i, q1r, q1i); kron_step<4>(Tr, Ti, q0r, q0i, q1r, q1i);
        // Final kron step (qubit8 -> in-pack half) directly into packed regs.
        load_q(xb, srot, 8, q0r, q0i, q1r, q1i);
        ull qr2 = pk2(q0r, q1r), qi2 = pk2(q0i, q1i);
#pragma unroll
        for (int p = 0; p < 8; p++) {
            ull TR = bc2(Tr[p]), TI = bc2(Ti[p]), nTI = bc2(-Ti[p]);
            aR[p] = f2fma(TR, qr2, f2mul(nTI, qi2));
            aI[p] = f2fma(TR, qi2, f2mul(TI,  qr2));
        }
    }
    {   // multiply by lane factor F
        ull FR = bc2(Fr), FI = bc2(Fi), nFI = bc2(-Fi);
#pragma unroll
        for (int p = 0; p < 8; p++) {
            ull r = aR[p], i = aI[p];
            aR[p] = f2fma(FR, r, f2mul(nFI, i));
            aI[p] = f2fma(FR, i, f2mul(FI,  r));
        }
    }

    // ---- Ring r=1 (pure-lane group virtual -> relabel Q1L) ----
    cnot_lpar_pk<lrow5(1, 0), 3>(aR, aI, lane);   // (4,3)
    cnot_local_pk<3, 2>(aR, aI);
    cnot_local_pk<2, 1>(aR, aI);
    cnot_local_pk<1, 0>(aR, aI);
    // (0,8): merged into layer-1 qubit0 rotation (SWAPMASK local bit0).

    // ---- Rotation layer 1 (under relabel Q1L) ----
    {
        const float* rm = srot + 1 * 72;
        rot_lane_pk<lmap(1, 16), lrow5(1, 4), 0xAAAA>(aR, aI, rm + 0 * 8, lane); // q0 (+CNOT(0,8))
        rot_lane_pk<lmap(1,  8), lrow5(1, 3), 0>(aR, aI, rm + 1 * 8, lane);      // q1
        rot_lane_pk<lmap(1,  4), lrow5(1, 2), 0>(aR, aI, rm + 2 * 8, lane);      // q2
        rot_lane_pk<lmap(1,  2), lrow5(1, 1), 0>(aR, aI, rm + 3 * 8, lane);      // q3
        rot_lane_pk<lmap(1,  1), lrow5(1, 0), 0>(aR, aI, rm + 4 * 8, lane);      // q4
        rot_local_pk<3>(aR, aI, rm + 5 * 8);                                     // q5
        rot_local_pk<2>(aR, aI, rm + 6 * 8);                                     // q6
        rot_local_pk<1>(aR, aI, rm + 7 * 8);                                     // q7
        rot_local0_pk(aR, aI, rm + 8 * 8);                                       // q8
    }

    // ---- Ring r=2 (pure-lane group virtual -> relabel Q2L) ----
    cnot_lpar_pk<lrow5(2, 1), 3>(aR, aI, lane);   // (5,3)
    cnot_lpar_pk<lrow5(2, 0), 2>(aR, aI, lane);   // (4,2)
    cnot_local_pk<3, 1>(aR, aI);
    cnot_local_pk<2, 0>(aR, aI);
    // (1,8) merged into layer-2 q0 rot (local bit1); (0,7) into q1 rot (bit0).

    // ---- Rotation layer 2 (under relabel Q2L) ----
    {
        const float* rm = srot + 2 * 72;
        rot_lane_pk<lmap(2, 16), lrow5(2, 4), 0xCCCC>(aR, aI, rm + 0 * 8, lane); // q0 (+CNOT(1,8))
        rot_lane_pk<lmap(2,  8), lrow5(2, 3), 0xAAAA>(aR, aI, rm + 1 * 8, lane); // q1 (+CNOT(0,7))
        rot_lane_pk<lmap(2,  4), lrow5(2, 2), 0>(aR, aI, rm + 2 * 8, lane);      // q2
        rot_lane_pk<lmap(2,  2), lrow5(2, 1), 0>(aR, aI, rm + 3 * 8, lane);      // q3
        rot_lane_pk<lmap(2,  1), lrow5(2, 0), 0>(aR, aI, rm + 4 * 8, lane);      // q4
        rot_local_pk<3>(aR, aI, rm + 5 * 8);
        rot_local_pk<2>(aR, aI, rm + 6 * 8);
        rot_local_pk<1>(aR, aI, rm + 7 * 8);
        rot_local0_pk(aR, aI, rm + 8 * 8);
    }

    // ---- Measurement (relabel + final CNOT ring folded into parity masks) ----
    ull p2[8];
#pragma unroll
    for (int p = 0; p < 8; p++)
        p2[p] = f2fma(aR[p], aR[p], f2mul(aI[p], aI[p]));

    float r0, r1, r2, r3, r4, r5, r6, r7, r8;
    meas_pk<0>(p2, lane, r0);
    meas_pk<1>(p2, lane, r1);
    meas_pk<2>(p2, lane, r2);
    meas_pk<3>(p2, lane, r3);
    meas_pk<4>(p2, lane, r4);
    meas_pk<5>(p2, lane, r5);
    meas_pk<6>(p2, lane, r6);
    meas_pk<7>(p2, lane, r7);
    meas_pk<8>(p2, lane, r8);

    if (lane < 9) {
        float v = (lane == 0) ? r0 : (lane == 1) ? r1 : (lane == 2) ? r2 :
                  (lane == 3) ? r3 : (lane == 4) ? r4 : (lane == 5) ? r5 :
                  (lane == 6) ? r6 : (lane == 7) ? r7 : r8;
        out[b * 9 + lane] = v;
    }
}

extern "C" void kernel_launch(void* const* d_in, const int* in_sizes, int n_in,
                              void* d_out, int out_size) {
    const float* x = (const float*)d_in[0];       // [nsamples, 9] fp32
    const float* w = (const float*)d_in[1];       // [3, 9, 3] fp32
    float* out = (float*)d_out;                   // [nsamples, 9] fp32
    int nsamples = in_sizes[0] / 9;

    prep_kernel<<<1, 32>>>(w);
    int nblocks = (nsamples + 7) / 8;
    sim_kernel<<<nblocks, 256>>>(x, out, nsamples);
}